// round 4
// baseline (speedup 1.0000x reference)
#include <cuda_runtime.h>
#include <cuda_bf16.h>

// BCE_for_non_zero: mean over [B,14] of BCE-with-logits * per-row group mask.
//
//   loss_sum = sum_c bce_c * m_c
//            = ln2 * ( sum_c L_c  -  sum_{g in {1,2,3}, gsum_g<=0} S_g )  -  sum_c x_c*t_c
//   where L_c = lg2(1 + 2^(x_c*log2e))  (softplus in log2 domain; inputs are
//   N(0,1) so no overflow), S_g = group sums of L, and the x*t term needs NO
//   mask because t_c>0 implies its group's target-sum > 0 implies m_c=1.
//
// Issue-bound fix (R3 ncu: issue=79%, DRAM=60%): one-hot FFMA routing instead
// of select chains, packed f32x2 math on column pairs, log2-domain softplus.

#define C 14
#define NPAIR 7
#define TILE_ROWS 128
#define THREADS 128
#define STAGE_FLOATS (TILE_ROWS * C)      // 1792
#define STAGE_CHUNKS (STAGE_FLOATS / 4)   // 448 16B chunks per array per stage
#define GRID_CTAS 1036                    // 148 SMs x 7 (grid-stride, balanced)

__device__ double g_acc;
__device__ unsigned int g_count;

typedef unsigned long long u64;

__device__ __forceinline__ u64 pack2(float a, float b) {
    u64 r; asm("mov.b64 %0, {%1,%2};" : "=l"(r) : "f"(a), "f"(b)); return r;
}
__device__ __forceinline__ void unpack2(u64 v, float& a, float& b) {
    asm("mov.b64 {%0,%1}, %2;" : "=f"(a), "=f"(b) : "l"(v));
}
__device__ __forceinline__ u64 mul2(u64 a, u64 b) {
    u64 r; asm("mul.rn.f32x2 %0, %1, %2;" : "=l"(r) : "l"(a), "l"(b)); return r;
}
__device__ __forceinline__ u64 add2(u64 a, u64 b) {
    u64 r; asm("add.rn.f32x2 %0, %1, %2;" : "=l"(r) : "l"(a), "l"(b)); return r;
}
__device__ __forceinline__ u64 fma2(u64 a, u64 b, u64 c) {
    u64 r; asm("fma.rn.f32x2 %0, %1, %2, %3;" : "=l"(r) : "l"(a), "l"(b), "l"(c)); return r;
}
__device__ __forceinline__ float ex2f(float x) {
    float r; asm("ex2.approx.f32 %0, %1;" : "=f"(r) : "f"(x)); return r;
}
__device__ __forceinline__ float lg2f(float x) {
    float r; asm("lg2.approx.f32 %0, %1;" : "=f"(r) : "f"(x)); return r;
}
__device__ __forceinline__ float hadd2(u64 v) {
    float a, b; unpack2(v, a, b); return a + b;
}
__device__ __forceinline__ unsigned smem_u32(const void* p) {
    return (unsigned)__cvta_generic_to_shared(p);
}

__device__ __forceinline__ void stage_tile(
    const float* __restrict__ gx, const float* __restrict__ gt,
    unsigned sxa, unsigned sta, int fullChunks)
{
#pragma unroll
    for (int k = 0; k < 7; k++) {
        int i = threadIdx.x + k * THREADS;        // 0 .. 895
        if (i < STAGE_CHUNKS) {
            if (i < fullChunks)
                asm volatile("cp.async.cg.shared.global [%0], [%1], 16;"
                             :: "r"(sxa + i * 16), "l"(gx + i * 4));
        } else {
            int j = i - STAGE_CHUNKS;
            if (j < fullChunks)
                asm volatile("cp.async.cg.shared.global [%0], [%1], 16;"
                             :: "r"(sta + j * 16), "l"(gt + j * 4));
        }
    }
}

__global__ void __launch_bounds__(THREADS) bce_fused_kernel(
    const float* __restrict__ x,
    const float* __restrict__ t,
    const int* __restrict__ groups,
    float* __restrict__ out,
    int B, double inv_n)
{
    __shared__ float sx[2][STAGE_FLOATS];
    __shared__ float st[2][STAGE_FLOATS];
    __shared__ int sg[C];
    __shared__ float warp_sums[THREADS / 32];

    if (threadIdx.x < C) sg[threadIdx.x] = groups[threadIdx.x];
    __syncthreads();

    // one-hot routing weights per column pair (packed f32x2), built once
    u64 w1[NPAIR], w2[NPAIR], w3[NPAIR];
#pragma unroll
    for (int p = 0; p < NPAIR; p++) {
        int ga = sg[2 * p], gb = sg[2 * p + 1];
        w1[p] = pack2(ga == 1 ? 1.0f : 0.0f, gb == 1 ? 1.0f : 0.0f);
        w2[p] = pack2(ga == 2 ? 1.0f : 0.0f, gb == 2 ? 1.0f : 0.0f);
        w3[p] = pack2(ga == 3 ? 1.0f : 0.0f, gb == 3 ? 1.0f : 0.0f);
    }

    const u64 LOG2E2 = pack2(1.4426950408889634f, 1.4426950408889634f);

    const long long nTiles = ((long long)B + TILE_ROWS - 1) / TILE_ROWS;
    const long long G = gridDim.x;

    const unsigned sxa0 = smem_u32(sx[0]);
    const unsigned sta0 = smem_u32(st[0]);
    const unsigned sxa1 = smem_u32(sx[1]);
    const unsigned sta1 = smem_u32(st[1]);

    auto tileRows = [&](long long tile) -> int {
        long long rem = (long long)B - tile * TILE_ROWS;
        return (rem < TILE_ROWS) ? (int)rem : TILE_ROWS;
    };
    auto tileChunks = [&](int rows) -> int {
        return (rows * (C * 4)) >> 4;
    };

    u64 Lacc = 0;   // packed (0.0f, 0.0f): running sum of lg2-softplus
    u64 XTacc = 0;  // packed running sum of x*t
    float dead = 0.0f;  // lg2-softplus sums of masked-out (dead) groups

    const long long t0 = blockIdx.x;
    if (t0 < nTiles)
        stage_tile(x + t0 * STAGE_FLOATS, t + t0 * STAGE_FLOATS,
                   sxa0, sta0, tileChunks(tileRows(t0)));
    asm volatile("cp.async.commit_group;");

    int buf = 0;
    for (long long tile = t0; tile < nTiles; tile += G) {
        const long long tn = tile + G;
        if (tn < nTiles)
            stage_tile(x + tn * STAGE_FLOATS, t + tn * STAGE_FLOATS,
                       buf ? sxa0 : sxa1, buf ? sta0 : sta1,
                       tileChunks(tileRows(tn)));
        asm volatile("cp.async.commit_group;");
        asm volatile("cp.async.wait_group 1;");
        __syncthreads();

        const int rows = tileRows(tile);
        const int fullFloats = tileChunks(rows) << 2;
        const int r = threadIdx.x;
        if (r < rows) {
            const int base = r * C;
            u64 xa[NPAIR], ta[NPAIR];
            if (base + C <= fullFloats) {
                // whole row staged; row base r*56 is 8B-aligned -> LDS.64
                const u64* px = (const u64*)(sx[buf] + base);
                const u64* pt = (const u64*)(st[buf] + base);
#pragma unroll
                for (int p = 0; p < NPAIR; p++) { xa[p] = px[p]; ta[p] = pt[p]; }
            } else {
                // rare tail: row valid in global, not fully staged
                const float* gxr = x + tile * STAGE_FLOATS + base;
                const float* gtr = t + tile * STAGE_FLOATS + base;
#pragma unroll
                for (int p = 0; p < NPAIR; p++) {
                    xa[p] = pack2(__ldg(gxr + 2 * p), __ldg(gxr + 2 * p + 1));
                    ta[p] = pack2(__ldg(gtr + 2 * p), __ldg(gtr + 2 * p + 1));
                }
            }

            u64 S1, S2, S3, G1, G2, G3;
#pragma unroll
            for (int p = 0; p < NPAIR; p++) {
                // L = lg2(1 + 2^(x*log2e))  (scalar MUFU halves)
                u64 y = mul2(xa[p], LOG2E2);
                float ylo, yhi; unpack2(y, ylo, yhi);
                float llo = lg2f(1.0f + ex2f(ylo));
                float lhi = lg2f(1.0f + ex2f(yhi));
                u64 L2 = pack2(llo, lhi);

                Lacc  = add2(Lacc, L2);
                XTacc = fma2(xa[p], ta[p], XTacc);
                if (p == 0) {
                    S1 = mul2(w1[0], L2);   G1 = mul2(w1[0], ta[0]);
                    S2 = mul2(w2[0], L2);   G2 = mul2(w2[0], ta[0]);
                    S3 = mul2(w3[0], L2);   G3 = mul2(w3[0], ta[0]);
                } else {
                    S1 = fma2(w1[p], L2, S1);  G1 = fma2(w1[p], ta[p], G1);
                    S2 = fma2(w2[p], L2, S2);  G2 = fma2(w2[p], ta[p], G2);
                    S3 = fma2(w3[p], L2, S3);  G3 = fma2(w3[p], ta[p], G3);
                }
            }
            // dead groups: target-sum == 0 -> their softplus sum is masked out
            float gh1 = hadd2(G1), gh2 = hadd2(G2), gh3 = hadd2(G3);
            dead += (gh1 > 0.0f) ? 0.0f : hadd2(S1);
            dead += (gh2 > 0.0f) ? 0.0f : hadd2(S2);
            dead += (gh3 > 0.0f) ? 0.0f : hadd2(S3);
        }
        __syncthreads();
        buf ^= 1;
    }

    // per-thread scalar:  ln2*(sum L - dead) - sum x*t
    float s = 0.6931471805599453f * (hadd2(Lacc) - dead) - hadd2(XTacc);

#pragma unroll
    for (int off = 16; off > 0; off >>= 1)
        s += __shfl_down_sync(0xFFFFFFFFu, s, off);

    const int lane = threadIdx.x & 31;
    const int wid  = threadIdx.x >> 5;
    if (lane == 0) warp_sums[wid] = s;
    __syncthreads();

    if (threadIdx.x == 0) {
        float v = 0.0f;
#pragma unroll
        for (int w = 0; w < THREADS / 32; w++) v += warp_sums[w];
        atomicAdd(&g_acc, (double)v);

        __threadfence();
        unsigned prev = atomicAdd(&g_count, 1u);
        if (prev == gridDim.x - 1) {
            __threadfence();
            out[0] = (float)(g_acc * inv_n);
            g_acc = 0.0;
            g_count = 0u;
        }
    }
}

extern "C" void kernel_launch(void* const* d_in, const int* in_sizes, int n_in,
                              void* d_out, int out_size)
{
    const float* x      = (const float*)d_in[0];
    const float* t      = (const float*)d_in[1];
    const int*   groups = (const int*)d_in[2];
    float* out = (float*)d_out;

    const long long total = in_sizes[0];   // B * C
    const int B = (int)(total / C);
    const double inv_n = 1.0 / (double)((long long)B * C);

    bce_fused_kernel<<<GRID_CTAS, THREADS>>>(x, t, groups, out, B, inv_n);
}

// round 5
// speedup vs baseline: 1.1698x; 1.1698x over previous
#include <cuda_runtime.h>
#include <cuda_bf16.h>

// BCE_for_non_zero: mean over [B,14] of BCE-with-logits * per-row group mask.
//
//   sum_c bce_c*m_c = ln2 * sum_kept lg2(1 + 2^(x*log2e)) - sum_c x_c*t_c
//   (x*t needs no mask: t>0 implies its group's sum>0 implies m=1; t in {0,1})
//
// Fast path is specialized on the known fixed group pattern
// [0,1,1,2,2,0,3,3,1,2,0,3,1,2] (verified at runtime; __noinline__ generic
// fallback otherwise) -> group sums are plain scalar adds, no routing weights.
//
// Per-WARP double-buffered cp.async staging (32 rows/block/warp, coalesced
// 16B chunks), no __syncthreads in the main loop -> warps slip independently.

#define C 14
#define THREADS 128
#define WARPS 4
#define GRID_CTAS 1036            // 148 SMs x 7 resident CTAs
#define ROW_FLOATS 448            // 32 rows * 14
#define CHUNKS_PER_ARR 112        // 448 floats / 4 per 16B chunk

__device__ double g_acc;
__device__ unsigned int g_count;

typedef unsigned long long u64;

__device__ __forceinline__ u64 pack2(float a, float b) {
    u64 r; asm("mov.b64 %0, {%1,%2};" : "=l"(r) : "f"(a), "f"(b)); return r;
}
__device__ __forceinline__ void unpack2(u64 v, float& a, float& b) {
    asm("mov.b64 {%0,%1}, %2;" : "=f"(a), "=f"(b) : "l"(v));
}
__device__ __forceinline__ u64 mul2(u64 a, u64 b) {
    u64 r; asm("mul.rn.f32x2 %0, %1, %2;" : "=l"(r) : "l"(a), "l"(b)); return r;
}
__device__ __forceinline__ u64 fma2(u64 a, u64 b, u64 c) {
    u64 r; asm("fma.rn.f32x2 %0, %1, %2, %3;" : "=l"(r) : "l"(a), "l"(b), "l"(c)); return r;
}
__device__ __forceinline__ float ex2f(float x) {
    float r; asm("ex2.approx.f32 %0, %1;" : "=f"(r) : "f"(x)); return r;
}
__device__ __forceinline__ float lg2f(float x) {
    float r; asm("lg2.approx.f32 %0, %1;" : "=f"(r) : "f"(x)); return r;
}
__device__ __forceinline__ float hadd2(u64 v) {
    float a, b; unpack2(v, a, b); return a + b;
}
__device__ __forceinline__ unsigned smem_u32(const void* p) {
    return (unsigned)__cvta_generic_to_shared(p);
}

// Generic fallback (any groups); never taken for this dataset.
__device__ __noinline__ float generic_rows(
    const float* __restrict__ x, const float* __restrict__ t,
    const int* __restrict__ groups, int B)
{
    int gl[C];
#pragma unroll
    for (int c = 0; c < C; c++) gl[c] = groups[c];
    float s = 0.0f;
    const long long stride = (long long)gridDim.x * blockDim.x;
    for (long long r = (long long)blockIdx.x * blockDim.x + threadIdx.x;
         r < B; r += stride) {
        float xv[C], tv[C];
#pragma unroll
        for (int c = 0; c < C; c++) {
            xv[c] = __ldg(x + r * C + c);
            tv[c] = __ldg(t + r * C + c);
        }
        float g1 = 0.f, g2 = 0.f, g3 = 0.f;
#pragma unroll
        for (int c = 0; c < C; c++) {
            int g = gl[c];
            g1 += (g == 1) ? tv[c] : 0.f;
            g2 += (g == 2) ? tv[c] : 0.f;
            g3 += (g == 3) ? tv[c] : 0.f;
        }
        float m1 = g1 > 0.f ? 1.f : 0.f, m2 = g2 > 0.f ? 1.f : 0.f,
              m3 = g3 > 0.f ? 1.f : 0.f;
#pragma unroll
        for (int c = 0; c < C; c++) {
            float xx = xv[c];
            float L = 0.6931471805599453f *
                      lg2f(1.0f + ex2f(xx * 1.4426950408889634f));
            float bce = L - xx * tv[c];
            int g = gl[c];
            float m = (g == 0) ? 1.f : (g == 1) ? m1 : (g == 2) ? m2 : m3;
            s += bce * m;
        }
    }
    return s;
}

__global__ void __launch_bounds__(THREADS, 7) bce_fused_kernel(
    const float* __restrict__ x,
    const float* __restrict__ t,
    const int* __restrict__ groups,
    float* __restrict__ out,
    int B, double inv_n)
{
    // per-warp double-buffered staging: [warp][stage][array][448 floats]
    __shared__ float sbuf[WARPS][2][2][ROW_FLOATS];
    __shared__ float warp_sums[WARPS];

    const int lane = threadIdx.x & 31;
    const int wid  = threadIdx.x >> 5;

    // fixed group pattern check (uniform across all threads)
    const bool fast =
        groups[0] == 0 && groups[1] == 1 && groups[2] == 1 && groups[3] == 2 &&
        groups[4] == 2 && groups[5] == 0 && groups[6] == 3 && groups[7] == 3 &&
        groups[8] == 1 && groups[9] == 2 && groups[10] == 0 && groups[11] == 3 &&
        groups[12] == 1 && groups[13] == 2;

    float s = 0.0f;

    if (fast) {
        const long long gw = (long long)blockIdx.x * WARPS + wid;
        const long long W  = (long long)gridDim.x * WARPS;
        const long long nBlk = ((long long)B + 31) >> 5;

        const u64 LOG2E2 = pack2(1.4426950408889634f, 1.4426950408889634f);
        u64 XT = 0;          // packed running sum of x*t
        float Lkept = 0.0f;  // running sum of kept lg2-softplus

        // stage one 32-row block for this warp into stage 'stg'
        auto stage = [&](long long wb, int stg) {
            if (wb < nBlk) {
                long long rem = (long long)B - (wb << 5);
                if (rem >= 32) {
                    const float* gx = x + wb * ROW_FLOATS;
                    const float* gt = t + wb * ROW_FLOATS;
                    const unsigned sxa = smem_u32(&sbuf[wid][stg][0][0]);
                    const unsigned sta = smem_u32(&sbuf[wid][stg][1][0]);
#pragma unroll
                    for (int j = 0; j < 7; j++) {
                        int c = lane + 32 * j;
                        if (c < CHUNKS_PER_ARR)
                            asm volatile("cp.async.cg.shared.global [%0], [%1], 16;"
                                         :: "r"(sxa + c * 16), "l"(gx + c * 4));
                        else
                            asm volatile("cp.async.cg.shared.global [%0], [%1], 16;"
                                         :: "r"(sta + (c - CHUNKS_PER_ARR) * 16),
                                            "l"(gt + (c - CHUNKS_PER_ARR) * 4));
                    }
                }
            }
            asm volatile("cp.async.commit_group;");
        };

        // groups: [0,1,1,2,2,0,3,3,1,2,0,3,1,2]
        auto row_compute = [&](const u64* X, const u64* T) {
            float L[2 * C / 2 * 1];  // 14
            float Lv[C];
#pragma unroll
            for (int p = 0; p < 7; p++) {
                u64 y = mul2(X[p], LOG2E2);
                float ylo, yhi; unpack2(y, ylo, yhi);
                Lv[2 * p]     = lg2f(1.0f + ex2f(ylo));
                Lv[2 * p + 1] = lg2f(1.0f + ex2f(yhi));
                XT = fma2(X[p], T[p], XT);
            }
            (void)L;
            float tv[C];
#pragma unroll
            for (int p = 0; p < 7; p++) unpack2(T[p], tv[2 * p], tv[2 * p + 1]);

            // static group membership
            float S0 = Lv[0] + Lv[5] + Lv[10];
            float S1 = (Lv[1] + Lv[2]) + (Lv[8] + Lv[12]);
            float S2 = (Lv[3] + Lv[4]) + (Lv[9] + Lv[13]);
            float S3 = Lv[6] + Lv[7] + Lv[11];
            float gs1 = (tv[1] + tv[2]) + (tv[8] + tv[12]);
            float gs2 = (tv[3] + tv[4]) + (tv[9] + tv[13]);
            float gs3 = tv[6] + tv[7] + tv[11];
            float k1 = (gs1 > 0.0f) ? S1 : 0.0f;
            float k2 = (gs2 > 0.0f) ? S2 : 0.0f;
            float k3 = (gs3 > 0.0f) ? S3 : 0.0f;
            Lkept += (S0 + k1) + (k2 + k3);
        };

        // prologue
        stage(gw, 0);
        int stg = 0;
        for (long long wb = gw; wb < nBlk; wb += W) {
            stage(wb + W, stg ^ 1);
            asm volatile("cp.async.wait_group 1;");
            __syncwarp();

            long long rem = (long long)B - (wb << 5);
            if (rem >= 32) {
                const u64* X = (const u64*)&sbuf[wid][stg][0][lane * C];
                const u64* T = (const u64*)&sbuf[wid][stg][1][lane * C];
                u64 Xr[7], Tr[7];
#pragma unroll
                for (int p = 0; p < 7; p++) { Xr[p] = X[p]; Tr[p] = T[p]; }
                row_compute(Xr, Tr);
            } else if (lane < (int)rem) {
                // tail block: direct global scalar loads
                const float* gx = x + (wb << 5) * C + lane * C;
                const float* gt = t + (wb << 5) * C + lane * C;
                u64 Xr[7], Tr[7];
#pragma unroll
                for (int p = 0; p < 7; p++) {
                    Xr[p] = pack2(__ldg(gx + 2 * p), __ldg(gx + 2 * p + 1));
                    Tr[p] = pack2(__ldg(gt + 2 * p), __ldg(gt + 2 * p + 1));
                }
                row_compute(Xr, Tr);
            }
            __syncwarp();
            stg ^= 1;
        }

        s = 0.6931471805599453f * Lkept - hadd2(XT);
    } else {
        s = generic_rows(x, t, groups, B);
    }

    // block reduction
#pragma unroll
    for (int off = 16; off > 0; off >>= 1)
        s += __shfl_down_sync(0xFFFFFFFFu, s, off);
    if (lane == 0) warp_sums[wid] = s;
    __syncthreads();

    if (threadIdx.x == 0) {
        float v = (warp_sums[0] + warp_sums[1]) + (warp_sums[2] + warp_sums[3]);
        atomicAdd(&g_acc, (double)v);
        __threadfence();
        unsigned prev = atomicAdd(&g_count, 1u);
        if (prev == gridDim.x - 1) {
            __threadfence();
            out[0] = (float)(g_acc * inv_n);
            g_acc = 0.0;
            g_count = 0u;
        }
    }
}

extern "C" void kernel_launch(void* const* d_in, const int* in_sizes, int n_in,
                              void* d_out, int out_size)
{
    const float* x      = (const float*)d_in[0];
    const float* t      = (const float*)d_in[1];
    const int*   groups = (const int*)d_in[2];
    float* out = (float*)d_out;

    const long long total = in_sizes[0];   // B * C
    const int B = (int)(total / C);
    const double inv_n = 1.0 / (double)((long long)B * C);

    bce_fused_kernel<<<GRID_CTAS, THREADS>>>(x, t, groups, out, B, inv_n);
}

// round 6
// speedup vs baseline: 1.1725x; 1.0023x over previous
#include <cuda_runtime.h>
#include <cuda_bf16.h>

// BCE_for_non_zero: mean over [B,14] of BCE-with-logits * per-row group mask.
//
//   sum_c bce_c*m_c = ln2 * sum_kept lg2(1 + 2^(x*log2e)) - sum_c x_c*t_c
//   (x*t needs no mask: t>0 implies its group's sum>0 implies m=1; t in {0,1})
//
// Fast path specialized on the fixed group pattern [0,1,1,2,2,0,3,3,1,2,0,3,1,2]
// (verified at runtime; __noinline__ generic fallback otherwise).
//
// Per-WARP 3-stage cp.async ring (32 rows/stage, wait_group 2 -> two stages
// in flight during compute), no block barriers in the main loop.
// 5 CTAs/SM x 4 warps = 20 warps/SM, ~143 KB/SM of loads in flight.

#define C 14
#define THREADS 128
#define WARPS 4
#define NSTAGES 3
#define CTAS_PER_SM 5
#define GRID_CTAS (148 * CTAS_PER_SM)   // 740
#define ROW_FLOATS 448                  // 32 rows * 14
#define CHUNKS_PER_ARR 112              // 448 floats / 4 per 16B chunk

__device__ double g_acc;
__device__ unsigned int g_count;

typedef unsigned long long u64;

__device__ __forceinline__ u64 pack2(float a, float b) {
    u64 r; asm("mov.b64 %0, {%1,%2};" : "=l"(r) : "f"(a), "f"(b)); return r;
}
__device__ __forceinline__ void unpack2(u64 v, float& a, float& b) {
    asm("mov.b64 {%0,%1}, %2;" : "=f"(a), "=f"(b) : "l"(v));
}
__device__ __forceinline__ u64 mul2(u64 a, u64 b) {
    u64 r; asm("mul.rn.f32x2 %0, %1, %2;" : "=l"(r) : "l"(a), "l"(b)); return r;
}
__device__ __forceinline__ u64 fma2(u64 a, u64 b, u64 c) {
    u64 r; asm("fma.rn.f32x2 %0, %1, %2, %3;" : "=l"(r) : "l"(a), "l"(b), "l"(c)); return r;
}
__device__ __forceinline__ float ex2f(float x) {
    float r; asm("ex2.approx.f32 %0, %1;" : "=f"(r) : "f"(x)); return r;
}
__device__ __forceinline__ float lg2f(float x) {
    float r; asm("lg2.approx.f32 %0, %1;" : "=f"(r) : "f"(x)); return r;
}
__device__ __forceinline__ float hadd2(u64 v) {
    float a, b; unpack2(v, a, b); return a + b;
}
__device__ __forceinline__ unsigned smem_u32(const void* p) {
    return (unsigned)__cvta_generic_to_shared(p);
}

// Generic fallback (any groups); never taken for this dataset.
__device__ __noinline__ float generic_rows(
    const float* __restrict__ x, const float* __restrict__ t,
    const int* __restrict__ groups, int B)
{
    int gl[C];
#pragma unroll
    for (int c = 0; c < C; c++) gl[c] = groups[c];
    float s = 0.0f;
    const long long stride = (long long)gridDim.x * blockDim.x;
    for (long long r = (long long)blockIdx.x * blockDim.x + threadIdx.x;
         r < B; r += stride) {
        float xv[C], tv[C];
#pragma unroll
        for (int c = 0; c < C; c++) {
            xv[c] = __ldg(x + r * C + c);
            tv[c] = __ldg(t + r * C + c);
        }
        float g1 = 0.f, g2 = 0.f, g3 = 0.f;
#pragma unroll
        for (int c = 0; c < C; c++) {
            int g = gl[c];
            g1 += (g == 1) ? tv[c] : 0.f;
            g2 += (g == 2) ? tv[c] : 0.f;
            g3 += (g == 3) ? tv[c] : 0.f;
        }
        float m1 = g1 > 0.f ? 1.f : 0.f, m2 = g2 > 0.f ? 1.f : 0.f,
              m3 = g3 > 0.f ? 1.f : 0.f;
#pragma unroll
        for (int c = 0; c < C; c++) {
            float xx = xv[c];
            float L = 0.6931471805599453f *
                      lg2f(1.0f + ex2f(xx * 1.4426950408889634f));
            float bce = L - xx * tv[c];
            int g = gl[c];
            float m = (g == 0) ? 1.f : (g == 1) ? m1 : (g == 2) ? m2 : m3;
            s += bce * m;
        }
    }
    return s;
}

__global__ void __launch_bounds__(THREADS, CTAS_PER_SM) bce_fused_kernel(
    const float* __restrict__ x,
    const float* __restrict__ t,
    const int* __restrict__ groups,
    float* __restrict__ out,
    int B, double inv_n)
{
    // per-warp 3-stage ring: [warp][stage][array][448 floats]  (42 KB)
    __shared__ float sbuf[WARPS][NSTAGES][2][ROW_FLOATS];
    __shared__ float warp_sums[WARPS];

    const int lane = threadIdx.x & 31;
    const int wid  = threadIdx.x >> 5;

    const bool fast =
        groups[0] == 0 && groups[1] == 1 && groups[2] == 1 && groups[3] == 2 &&
        groups[4] == 2 && groups[5] == 0 && groups[6] == 3 && groups[7] == 3 &&
        groups[8] == 1 && groups[9] == 2 && groups[10] == 0 && groups[11] == 3 &&
        groups[12] == 1 && groups[13] == 2;

    float s = 0.0f;

    if (fast) {
        const long long gw = (long long)blockIdx.x * WARPS + wid;
        const long long W  = (long long)gridDim.x * WARPS;
        const long long nBlk = ((long long)B + 31) >> 5;

        const u64 LOG2E2 = pack2(1.4426950408889634f, 1.4426950408889634f);
        u64 XT = 0;          // packed running sum of x*t
        float Lkept = 0.0f;  // running sum of kept lg2-softplus

        // stage one 32-row block for this warp into ring slot 'stg';
        // always commits (keeps group counts aligned even past the end)
        auto stage = [&](long long wb, int stg) {
            if (wb < nBlk && ((long long)B - (wb << 5)) >= 32) {
                const float* gx = x + wb * ROW_FLOATS;
                const float* gt = t + wb * ROW_FLOATS;
                const unsigned sxa = smem_u32(&sbuf[wid][stg][0][0]);
                const unsigned sta = smem_u32(&sbuf[wid][stg][1][0]);
#pragma unroll
                for (int j = 0; j < 7; j++) {
                    int c = lane + 32 * j;
                    if (c < CHUNKS_PER_ARR)
                        asm volatile("cp.async.cg.shared.global [%0], [%1], 16;"
                                     :: "r"(sxa + c * 16), "l"(gx + c * 4));
                    else
                        asm volatile("cp.async.cg.shared.global [%0], [%1], 16;"
                                     :: "r"(sta + (c - CHUNKS_PER_ARR) * 16),
                                        "l"(gt + (c - CHUNKS_PER_ARR) * 4));
                }
            }
            asm volatile("cp.async.commit_group;");
        };

        // groups: [0,1,1,2,2,0,3,3,1,2,0,3,1,2]
        auto row_compute = [&](const u64* X, const u64* T) {
            float Lv[C];
#pragma unroll
            for (int p = 0; p < 7; p++) {
                u64 y = mul2(X[p], LOG2E2);
                float ylo, yhi; unpack2(y, ylo, yhi);
                Lv[2 * p]     = lg2f(1.0f + ex2f(ylo));
                Lv[2 * p + 1] = lg2f(1.0f + ex2f(yhi));
                XT = fma2(X[p], T[p], XT);
            }
            float tv[C];
#pragma unroll
            for (int p = 0; p < 7; p++) unpack2(T[p], tv[2 * p], tv[2 * p + 1]);

            float S0 = Lv[0] + Lv[5] + Lv[10];
            float S1 = (Lv[1] + Lv[2]) + (Lv[8] + Lv[12]);
            float S2 = (Lv[3] + Lv[4]) + (Lv[9] + Lv[13]);
            float S3 = Lv[6] + Lv[7] + Lv[11];
            float gs1 = (tv[1] + tv[2]) + (tv[8] + tv[12]);
            float gs2 = (tv[3] + tv[4]) + (tv[9] + tv[13]);
            float gs3 = tv[6] + tv[7] + tv[11];
            float k1 = (gs1 > 0.0f) ? S1 : 0.0f;
            float k2 = (gs2 > 0.0f) ? S2 : 0.0f;
            float k3 = (gs3 > 0.0f) ? S3 : 0.0f;
            Lkept += (S0 + k1) + (k2 + k3);
        };

        // prologue: fill slots 0 and 1
        stage(gw, 0);
        stage(gw + W, 1);

        int slot = 0;
        for (long long wb = gw; wb < nBlk; wb += W) {
            // keep two stages ahead in flight
            int nslot = slot + 2; if (nslot >= NSTAGES) nslot -= NSTAGES;
            stage(wb + 2 * W, nslot);
            asm volatile("cp.async.wait_group 2;");  // oldest (slot) is ready
            __syncwarp();

            long long rem = (long long)B - (wb << 5);
            if (rem >= 32) {
                const u64* X = (const u64*)&sbuf[wid][slot][0][lane * C];
                const u64* T = (const u64*)&sbuf[wid][slot][1][lane * C];
                u64 Xr[7], Tr[7];
#pragma unroll
                for (int p = 0; p < 7; p++) { Xr[p] = X[p]; Tr[p] = T[p]; }
                row_compute(Xr, Tr);
            } else if (lane < (int)rem) {
                // tail block: direct global scalar loads
                const float* gx = x + (wb << 5) * C + lane * C;
                const float* gt = t + (wb << 5) * C + lane * C;
                u64 Xr[7], Tr[7];
#pragma unroll
                for (int p = 0; p < 7; p++) {
                    Xr[p] = pack2(__ldg(gx + 2 * p), __ldg(gx + 2 * p + 1));
                    Tr[p] = pack2(__ldg(gt + 2 * p), __ldg(gt + 2 * p + 1));
                }
                row_compute(Xr, Tr);
            }
            __syncwarp();
            slot++; if (slot >= NSTAGES) slot = 0;
        }

        s = 0.6931471805599453f * Lkept - hadd2(XT);
    } else {
        s = generic_rows(x, t, groups, B);
    }

    // block reduction
#pragma unroll
    for (int off = 16; off > 0; off >>= 1)
        s += __shfl_down_sync(0xFFFFFFFFu, s, off);
    if (lane == 0) warp_sums[wid] = s;
    __syncthreads();

    if (threadIdx.x == 0) {
        float v = (warp_sums[0] + warp_sums[1]) + (warp_sums[2] + warp_sums[3]);
        atomicAdd(&g_acc, (double)v);
        __threadfence();
        unsigned prev = atomicAdd(&g_count, 1u);
        if (prev == gridDim.x - 1) {
            __threadfence();
            out[0] = (float)(g_acc * inv_n);
            g_acc = 0.0;
            g_count = 0u;
        }
    }
}

extern "C" void kernel_launch(void* const* d_in, const int* in_sizes, int n_in,
                              void* d_out, int out_size)
{
    const float* x      = (const float*)d_in[0];
    const float* t      = (const float*)d_in[1];
    const int*   groups = (const int*)d_in[2];
    float* out = (float*)d_out;

    const long long total = in_sizes[0];   // B * C
    const int B = (int)(total / C);
    const double inv_n = 1.0 / (double)((long long)B * C);

    bce_fused_kernel<<<GRID_CTAS, THREADS>>>(x, t, groups, out, B, inv_n);
}